// round 1
// baseline (speedup 1.0000x reference)
#include <cuda_runtime.h>
#include <cuda_bf16.h>

#define N_ELEMENT 8
#define N_LINES 32
#define MINIBATCH 512
#define SAMPLE_N 1024
#define N_VOXEL_MB (MINIBATCH * SAMPLE_N)
#define THREADS 256
// SAMPLE_CM / SAMPLE_N
#define ATT_SCALE (0.01f / 1024.0f)
// PROBE_I0 * DET_SOLID_ANGLE_RATIO * SIGNAL_ATT
#define OUT_SCALE (100000.0f * 0.05f * 1.0f)

__global__ __launch_bounds__(THREADS) void ppm_fused_kernel(
    const float* __restrict__ xp,        // [8, 512, 1024]
    const float* __restrict__ mu_probe,  // [8]
    const float* __restrict__ fl_unit,   // [32]
    const float* __restrict__ SA,        // [32, 524288]
    float* __restrict__ out)             // [32*512] fl_signal ++ [512] trans
{
    const int m    = blockIdx.x;
    const int t    = threadIdx.x;
    const int lane = t & 31;
    const int warp = t >> 5;

    __shared__ float warp_sums[8];
    __shared__ float line_part[N_LINES][8];

    // Each thread owns 4 consecutive n's: n0 = 4*t .. 4*t+3
    const int base = m * SAMPLE_N + t * 4;

    // ---- Load xp for all 8 elements (float4, fully coalesced) ----
    float4 v[N_ELEMENT];
    #pragma unroll
    for (int e = 0; e < N_ELEMENT; e++) {
        v[e] = *reinterpret_cast<const float4*>(xp + (size_t)e * N_VOXEL_MB + base);
    }

    // mu_probe: uniform addresses -> broadcast loads
    float mu[N_ELEMENT];
    #pragma unroll
    for (int e = 0; e < N_ELEMENT; e++) mu[e] = __ldg(mu_probe + e);

    // ---- Per-item weighted LAC: s_i = sum_e xp[e]*mu[e] ----
    float s0 = 0.f, s1 = 0.f, s2 = 0.f, s3 = 0.f;
    #pragma unroll
    for (int e = 0; e < N_ELEMENT; e++) {
        s0 = fmaf(v[e].x, mu[e], s0);
        s1 = fmaf(v[e].y, mu[e], s1);
        s2 = fmaf(v[e].z, mu[e], s2);
        s3 = fmaf(v[e].w, mu[e], s3);
    }

    // ---- Thread-local inclusive scan ----
    const float t0 = s0;
    const float t1 = t0 + s1;
    const float t2 = t1 + s2;
    const float t3 = t2 + s3;   // thread total

    // ---- Warp inclusive scan of thread totals ----
    float x = t3;
    #pragma unroll
    for (int off = 1; off < 32; off <<= 1) {
        float y = __shfl_up_sync(0xffffffffu, x, off);
        if (lane >= off) x += y;
    }
    if (lane == 31) warp_sums[warp] = x;
    __syncthreads();

    // ---- Cross-warp exclusive base + block total ----
    float wprev = 0.f, total = 0.f;
    #pragma unroll
    for (int w = 0; w < 8; w++) {
        float ws = warp_sums[w];
        total += ws;
        if (w < warp) wprev += ws;
    }
    const float excl = (x - t3) + wprev;   // exclusive prefix before item 0

    // ---- Attenuation (exclusive prefix per item) ----
    const float a0 = __expf(-excl * ATT_SCALE);
    const float a1 = __expf(-(excl + t0) * ATT_SCALE);
    const float a2 = __expf(-(excl + t1) * ATT_SCALE);
    const float a3 = __expf(-(excl + t2) * ATT_SCALE);

    // ---- Per-line accumulation: 4 lines share each element's weighted xp ----
    #pragma unroll
    for (int e = 0; e < N_ELEMENT; e++) {
        const float w0 = a0 * v[e].x;
        const float w1 = a1 * v[e].y;
        const float w2 = a2 * v[e].z;
        const float w3 = a3 * v[e].w;
        #pragma unroll
        for (int j = 0; j < 4; j++) {
            const int l = e * 4 + j;
            const float4 sa = *reinterpret_cast<const float4*>(
                SA + (size_t)l * N_VOXEL_MB + base);
            float acc = fmaf(w0, sa.x,
                        fmaf(w1, sa.y,
                        fmaf(w2, sa.z, w3 * sa.w)));
            // warp reduce
            #pragma unroll
            for (int off = 16; off; off >>= 1)
                acc += __shfl_xor_sync(0xffffffffu, acc, off);
            if (lane == 0) line_part[l][warp] = acc;
        }
    }
    __syncthreads();

    // ---- Finalize: 32 threads each sum 8 warp partials for one line ----
    if (t < N_LINES) {
        float s = 0.f;
        #pragma unroll
        for (int w = 0; w < 8; w++) s += line_part[t][w];
        out[t * MINIBATCH + m] = s * __ldg(fl_unit + t) * OUT_SCALE;
    }
    if (t == 0) {
        out[N_LINES * MINIBATCH + m] = total * ATT_SCALE;
    }
}

extern "C" void kernel_launch(void* const* d_in, const int* in_sizes, int n_in,
                              void* d_out, int out_size) {
    const float* xp       = (const float*)d_in[0];
    const float* mu_probe = (const float*)d_in[1];
    const float* fl_unit  = (const float*)d_in[2];
    const float* SA_theta = (const float*)d_in[3];
    float* out = (float*)d_out;
    (void)in_sizes; (void)n_in; (void)out_size;

    ppm_fused_kernel<<<MINIBATCH, THREADS>>>(xp, mu_probe, fl_unit, SA_theta, out);
}

// round 9
// speedup vs baseline: 1.0151x; 1.0151x over previous
#include <cuda_runtime.h>
#include <cuda_bf16.h>

#define N_ELEMENT 8
#define N_LINES 32
#define MINIBATCH 512
#define SAMPLE_N 1024
#define N_VOXEL_MB (MINIBATCH * SAMPLE_N)
#define THREADS 256
// SAMPLE_CM / SAMPLE_N
#define ATT_SCALE (0.01f / 1024.0f)
// PROBE_I0 * DET_SOLID_ANGLE_RATIO * SIGNAL_ATT
#define OUT_SCALE (100000.0f * 0.05f * 1.0f)

__global__ __launch_bounds__(THREADS) void ppm_fused_kernel(
    const float* __restrict__ xp,        // [8, 512, 1024]
    const float* __restrict__ mu_probe,  // [8]
    const float* __restrict__ fl_unit,   // [32]
    const float* __restrict__ SA,        // [32, 524288]
    float* __restrict__ out)             // [32*512] fl_signal ++ [512] trans
{
    const int m    = blockIdx.x;
    const int t    = threadIdx.x;
    const int lane = t & 31;
    const int warp = t >> 5;

    __shared__ float warp_sums[8];
    __shared__ float line_part[N_LINES][8];

    // Each thread owns 4 consecutive n's: n0 = 4*t .. 4*t+3
    const int base = m * SAMPLE_N + t * 4;

    // ---- Load xp for all 8 elements (float4, streaming, batched -> MLP=8) ----
    float4 v[N_ELEMENT];
    #pragma unroll
    for (int e = 0; e < N_ELEMENT; e++) {
        v[e] = __ldcs(reinterpret_cast<const float4*>(xp + (size_t)e * N_VOXEL_MB + base));
    }

    // mu_probe: uniform addresses -> broadcast loads
    float mu[N_ELEMENT];
    #pragma unroll
    for (int e = 0; e < N_ELEMENT; e++) mu[e] = __ldg(mu_probe + e);

    // ---- Per-item weighted LAC: s_i = sum_e xp[e]*mu[e] ----
    float s0 = 0.f, s1 = 0.f, s2 = 0.f, s3 = 0.f;
    #pragma unroll
    for (int e = 0; e < N_ELEMENT; e++) {
        s0 = fmaf(v[e].x, mu[e], s0);
        s1 = fmaf(v[e].y, mu[e], s1);
        s2 = fmaf(v[e].z, mu[e], s2);
        s3 = fmaf(v[e].w, mu[e], s3);
    }

    // ---- Thread-local inclusive scan ----
    const float t0 = s0;
    const float t1 = t0 + s1;
    const float t2 = t1 + s2;
    const float t3 = t2 + s3;   // thread total

    // ---- Warp inclusive scan of thread totals ----
    float x = t3;
    #pragma unroll
    for (int off = 1; off < 32; off <<= 1) {
        float y = __shfl_up_sync(0xffffffffu, x, off);
        if (lane >= off) x += y;
    }
    if (lane == 31) warp_sums[warp] = x;
    __syncthreads();

    // ---- Cross-warp exclusive base + block total ----
    float wprev = 0.f, total = 0.f;
    #pragma unroll
    for (int w = 0; w < 8; w++) {
        float ws = warp_sums[w];
        total += ws;
        if (w < warp) wprev += ws;
    }
    const float excl = (x - t3) + wprev;   // exclusive prefix before item 0

    // ---- Attenuation (exclusive prefix per item) ----
    const float a0 = __expf(-excl * ATT_SCALE);
    const float a1 = __expf(-(excl + t0) * ATT_SCALE);
    const float a2 = __expf(-(excl + t1) * ATT_SCALE);
    const float a3 = __expf(-(excl + t2) * ATT_SCALE);

    // ---- Per-line partials: loads batched 4-wide per element group, ----
    // ---- NO reduction inside the load loop (keeps MLP high).        ----
    float part[N_LINES];
    #pragma unroll
    for (int e = 0; e < N_ELEMENT; e++) {
        const float w0 = a0 * v[e].x;
        const float w1 = a1 * v[e].y;
        const float w2 = a2 * v[e].z;
        const float w3 = a3 * v[e].w;

        const float* sab = SA + (size_t)(e * 4) * N_VOXEL_MB + base;
        // batch all 4 line loads before consuming any
        const float4 sa0 = __ldcs(reinterpret_cast<const float4*>(sab + 0 * (size_t)N_VOXEL_MB));
        const float4 sa1 = __ldcs(reinterpret_cast<const float4*>(sab + 1 * (size_t)N_VOXEL_MB));
        const float4 sa2 = __ldcs(reinterpret_cast<const float4*>(sab + 2 * (size_t)N_VOXEL_MB));
        const float4 sa3 = __ldcs(reinterpret_cast<const float4*>(sab + 3 * (size_t)N_VOXEL_MB));

        part[e * 4 + 0] = fmaf(w0, sa0.x, fmaf(w1, sa0.y, fmaf(w2, sa0.z, w3 * sa0.w)));
        part[e * 4 + 1] = fmaf(w0, sa1.x, fmaf(w1, sa1.y, fmaf(w2, sa1.z, w3 * sa1.w)));
        part[e * 4 + 2] = fmaf(w0, sa2.x, fmaf(w1, sa2.y, fmaf(w2, sa2.z, w3 * sa2.w)));
        part[e * 4 + 3] = fmaf(w0, sa3.x, fmaf(w1, sa3.y, fmaf(w2, sa3.z, w3 * sa3.w)));
    }

    // ---- Deferred warp reductions: 32 independent shfl chains, pipelined ----
    #pragma unroll
    for (int l = 0; l < N_LINES; l++) {
        float acc = part[l];
        #pragma unroll
        for (int off = 16; off; off >>= 1)
            acc += __shfl_xor_sync(0xffffffffu, acc, off);
        if (lane == 0) line_part[l][warp] = acc;
    }
    __syncthreads();

    // ---- Finalize: 32 threads each sum 8 warp partials for one line ----
    if (t < N_LINES) {
        float s = 0.f;
        #pragma unroll
        for (int w = 0; w < 8; w++) s += line_part[t][w];
        out[t * MINIBATCH + m] = s * __ldg(fl_unit + t) * OUT_SCALE;
    }
    if (t == 0) {
        out[N_LINES * MINIBATCH + m] = total * ATT_SCALE;
    }
}

extern "C" void kernel_launch(void* const* d_in, const int* in_sizes, int n_in,
                              void* d_out, int out_size) {
    const float* xp       = (const float*)d_in[0];
    const float* mu_probe = (const float*)d_in[1];
    const float* fl_unit  = (const float*)d_in[2];
    const float* SA_theta = (const float*)d_in[3];
    float* out = (float*)d_out;
    (void)in_sizes; (void)n_in; (void)out_size;

    ppm_fused_kernel<<<MINIBATCH, THREADS>>>(xp, mu_probe, fl_unit, SA_theta, out);
}

// round 11
// speedup vs baseline: 1.3732x; 1.3528x over previous
#include <cuda_runtime.h>
#include <cuda_bf16.h>

#define N_ELEMENT 8
#define N_LINES 32
#define MINIBATCH 512
#define SAMPLE_N 1024
#define N_VOXEL_MB (MINIBATCH * SAMPLE_N)
#define THREADS 256
// SAMPLE_CM / SAMPLE_N
#define ATT_SCALE (0.01f / 1024.0f)
// PROBE_I0 * DET_SOLID_ANGLE_RATIO * SIGNAL_ATT
#define OUT_SCALE (100000.0f * 0.05f * 1.0f)

__global__ __launch_bounds__(THREADS) void ppm_fused_kernel(
    const float* __restrict__ xp,        // [8, 512, 1024]
    const float* __restrict__ mu_probe,  // [8]
    const float* __restrict__ fl_unit,   // [32]
    const float* __restrict__ SA,        // [32, 524288]
    float* __restrict__ out)             // [32*512] fl_signal ++ [512] trans
{
    const int m    = blockIdx.x;
    const int t    = threadIdx.x;
    const int lane = t & 31;
    const int warp = t >> 5;

    __shared__ float warp_sums[8];
    // attenuation-weighted xp: wsm[e][n] = atten[n] * xp[e][m][n]   (32 KB)
    __shared__ float wsm[N_ELEMENT][SAMPLE_N];

    // ======================= PHASE 1: scan + weight =======================
    // Each thread owns 4 consecutive n's: n0 = 4*t .. 4*t+3
    const int base = m * SAMPLE_N + t * 4;

    float4 v[N_ELEMENT];
    #pragma unroll
    for (int e = 0; e < N_ELEMENT; e++) {
        v[e] = *reinterpret_cast<const float4*>(xp + (size_t)e * N_VOXEL_MB + base);
    }

    float mu[N_ELEMENT];
    #pragma unroll
    for (int e = 0; e < N_ELEMENT; e++) mu[e] = __ldg(mu_probe + e);

    // per-item weighted LAC
    float s0 = 0.f, s1 = 0.f, s2 = 0.f, s3 = 0.f;
    #pragma unroll
    for (int e = 0; e < N_ELEMENT; e++) {
        s0 = fmaf(v[e].x, mu[e], s0);
        s1 = fmaf(v[e].y, mu[e], s1);
        s2 = fmaf(v[e].z, mu[e], s2);
        s3 = fmaf(v[e].w, mu[e], s3);
    }

    // thread-local inclusive scan
    const float t0 = s0;
    const float t1 = t0 + s1;
    const float t2 = t1 + s2;
    const float t3 = t2 + s3;

    // warp inclusive scan of thread totals
    float x = t3;
    #pragma unroll
    for (int off = 1; off < 32; off <<= 1) {
        float y = __shfl_up_sync(0xffffffffu, x, off);
        if (lane >= off) x += y;
    }
    if (lane == 31) warp_sums[warp] = x;
    __syncthreads();

    float wprev = 0.f, total = 0.f;
    #pragma unroll
    for (int w = 0; w < 8; w++) {
        float ws = warp_sums[w];
        total += ws;
        if (w < warp) wprev += ws;
    }
    const float excl = (x - t3) + wprev;   // exclusive prefix before item 0

    const float a0 = __expf(-excl * ATT_SCALE);
    const float a1 = __expf(-(excl + t0) * ATT_SCALE);
    const float a2 = __expf(-(excl + t1) * ATT_SCALE);
    const float a3 = __expf(-(excl + t2) * ATT_SCALE);

    // write weighted xp to SMEM (STS.128, conflict-free: consecutive threads,
    // consecutive 16B)
    #pragma unroll
    for (int e = 0; e < N_ELEMENT; e++) {
        float4 wv;
        wv.x = a0 * v[e].x;
        wv.y = a1 * v[e].y;
        wv.z = a2 * v[e].z;
        wv.w = a3 * v[e].w;
        *reinterpret_cast<float4*>(&wsm[e][t * 4]) = wv;
    }

    if (t == 0) {
        out[N_LINES * MINIBATCH + m] = total * ATT_SCALE;
    }
    __syncthreads();

    // ======================= PHASE 2: SA streaming ========================
    // Warp w owns element w's 4 lines (l = 4w..4w+3). It streams the whole
    // row (1024 n) in 8 chunks of 128; per chunk: 1 LDS.128 + 4 independent
    // LDG.E.128 into 4 scalar accumulators -> low live-set, deep pipelining.
    const float* sa_base = SA + (size_t)(warp * 4) * N_VOXEL_MB + m * SAMPLE_N;

    float acc0 = 0.f, acc1 = 0.f, acc2 = 0.f, acc3 = 0.f;
    #pragma unroll
    for (int c = 0; c < 8; c++) {
        const int n0 = c * 128 + lane * 4;
        const float4 wx  = *reinterpret_cast<const float4*>(&wsm[warp][n0]);
        const float4 sa0 = *reinterpret_cast<const float4*>(sa_base + 0 * (size_t)N_VOXEL_MB + n0);
        const float4 sa1 = *reinterpret_cast<const float4*>(sa_base + 1 * (size_t)N_VOXEL_MB + n0);
        const float4 sa2 = *reinterpret_cast<const float4*>(sa_base + 2 * (size_t)N_VOXEL_MB + n0);
        const float4 sa3 = *reinterpret_cast<const float4*>(sa_base + 3 * (size_t)N_VOXEL_MB + n0);

        acc0 = fmaf(wx.x, sa0.x, fmaf(wx.y, sa0.y, fmaf(wx.z, sa0.z, fmaf(wx.w, sa0.w, acc0))));
        acc1 = fmaf(wx.x, sa1.x, fmaf(wx.y, sa1.y, fmaf(wx.z, sa1.z, fmaf(wx.w, sa1.w, acc1))));
        acc2 = fmaf(wx.x, sa2.x, fmaf(wx.y, sa2.y, fmaf(wx.z, sa2.z, fmaf(wx.w, sa2.w, acc2))));
        acc3 = fmaf(wx.x, sa3.x, fmaf(wx.y, sa3.y, fmaf(wx.z, sa3.z, fmaf(wx.w, sa3.w, acc3))));
    }

    // 4 independent warp reductions, interleaved (pipelined through SHFL)
    #pragma unroll
    for (int off = 16; off; off >>= 1) {
        acc0 += __shfl_xor_sync(0xffffffffu, acc0, off);
        acc1 += __shfl_xor_sync(0xffffffffu, acc1, off);
        acc2 += __shfl_xor_sync(0xffffffffu, acc2, off);
        acc3 += __shfl_xor_sync(0xffffffffu, acc3, off);
    }

    if (lane == 0) {
        const int l = warp * 4;
        out[(l + 0) * MINIBATCH + m] = acc0 * __ldg(fl_unit + l + 0) * OUT_SCALE;
        out[(l + 1) * MINIBATCH + m] = acc1 * __ldg(fl_unit + l + 1) * OUT_SCALE;
        out[(l + 2) * MINIBATCH + m] = acc2 * __ldg(fl_unit + l + 2) * OUT_SCALE;
        out[(l + 3) * MINIBATCH + m] = acc3 * __ldg(fl_unit + l + 3) * OUT_SCALE;
    }
}

extern "C" void kernel_launch(void* const* d_in, const int* in_sizes, int n_in,
                              void* d_out, int out_size) {
    const float* xp       = (const float*)d_in[0];
    const float* mu_probe = (const float*)d_in[1];
    const float* fl_unit  = (const float*)d_in[2];
    const float* SA_theta = (const float*)d_in[3];
    float* out = (float*)d_out;
    (void)in_sizes; (void)n_in; (void)out_size;

    ppm_fused_kernel<<<MINIBATCH, THREADS>>>(xp, mu_probe, fl_unit, SA_theta, out);
}